// round 11
// baseline (speedup 1.0000x reference)
#include <cuda_runtime.h>
#include <cuda_bf16.h>
#include <cstddef>

#define NB 8
#define NH 96
#define NW 96
#define NC 512
#define NCQ 64
#define NT (NB*NH*NW)   // 73728 tokens

typedef unsigned long long u64;

// ---------------- scratch (device globals; no runtime allocation) --------
__device__ float g_q[(size_t)NT*NCQ];            // [t][64]
__device__ float g_k[(size_t)NT*NCQ];            // [t][64]
__device__ float g_v[(size_t)NT*NC];             // [t][512] (tf32-rounded)
__device__ float g_sv[(size_t)NB*NW*NH*NH];      // [b][w][h][g] RAW logits
__device__ float g_sh[(size_t)NT*NW];            // [b][h][w][u] RAW logits
__device__ __nv_bfloat16 g_yv[(size_t)NT*NC];    // [t][512] bf16 (residual path)

// ---------------- helpers ------------------------------------------------
__device__ __forceinline__ float to_tf32(float x) {
    unsigned u; asm("cvt.rna.tf32.f32 %0, %1;" : "=r"(u) : "f"(x));
    return __uint_as_float(u);
}
__device__ __forceinline__ void mma_tf32(float (&c)[4], const unsigned (&a)[4],
                                         const unsigned (&b)[2]) {
    asm volatile(
        "mma.sync.aligned.m16n8k8.row.col.f32.tf32.tf32.f32 "
        "{%0,%1,%2,%3}, {%4,%5,%6,%7}, {%8,%9}, {%0,%1,%2,%3};\n"
        : "+f"(c[0]), "+f"(c[1]), "+f"(c[2]), "+f"(c[3])
        : "r"(a[0]), "r"(a[1]), "r"(a[2]), "r"(a[3]),
          "r"(b[0]), "r"(b[1]));
}
__device__ __forceinline__ void cp16(void* s, const void* g) {
    unsigned sa = (unsigned)__cvta_generic_to_shared(s);
    asm volatile("cp.async.ca.shared.global [%0], [%1], 16;" :: "r"(sa), "l"(g));
}
__device__ __forceinline__ void cp_commit() {
    asm volatile("cp.async.commit_group;");
}
template<int N> __device__ __forceinline__ void cp_wait() {
    asm volatile("cp.async.wait_group %0;" :: "n"(N));
}

// =========================================================================
// Merged projection GEMM via tf32 mma, cp.async double-buffered (R9).
// grid (5, 576): blockIdx.x = 0..3 -> v chunk; = 4 -> q|k.
// BM=128, BK=16, 256 thr, warp grid 4m x 2n.
// =========================================================================
__global__ __launch_bounds__(256) void proj_kernel(
    const float* __restrict__ A,  const float* __restrict__ Wq,
    const float* __restrict__ Wk, const float* __restrict__ Wv,
    const float* __restrict__ bq, const float* __restrict__ bk,
    const float* __restrict__ bv)
{
    __shared__ float As[2][128 * 20];
    __shared__ float Bs[2][16 * 136];

    const int tid  = threadIdx.x;
    const int lane = tid & 31, wid = tid >> 5;
    const int wm = wid & 3, wn = wid >> 2;   // 4 x 2 warps, warp tile 32x64
    const int g = lane >> 2, t = lane & 3;
    const size_t bm = (size_t)blockIdx.y * 128;
    const int vmode = (blockIdx.x < 4);
    const int bn = vmode ? blockIdx.x * 128 : 0;

    const int am0 = tid >> 2,         ac0 = (tid & 3) * 4;
    const int am1 = (tid + 256) >> 2, ac1 = ((tid + 256) & 3) * 4;
    const int bk0 = tid >> 5,         bc0 = (tid & 31) * 4;
    const int bk1 = (tid + 256) >> 5, bc1 = ((tid + 256) & 31) * 4;

    #define PROJ_ISSUE(buf, k0)                                                  \
    {                                                                            \
        cp16(&As[buf][am0 * 20 + ac0], A + (bm + am0) * 512 + (k0) + ac0);       \
        cp16(&As[buf][am1 * 20 + ac1], A + (bm + am1) * 512 + (k0) + ac1);       \
        const float* s0, *s1;                                                    \
        if (vmode) {                                                             \
            s0 = Wv + (size_t)((k0) + bk0) * 512 + bn + bc0;                     \
            s1 = Wv + (size_t)((k0) + bk1) * 512 + bn + bc1;                     \
        } else {                                                                 \
            s0 = (bc0 < 64) ? (Wq + (size_t)((k0) + bk0) * 64 + bc0)             \
                            : (Wk + (size_t)((k0) + bk0) * 64 + bc0 - 64);       \
            s1 = (bc1 < 64) ? (Wq + (size_t)((k0) + bk1) * 64 + bc1)             \
                            : (Wk + (size_t)((k0) + bk1) * 64 + bc1 - 64);       \
        }                                                                        \
        cp16(&Bs[buf][bk0 * 136 + bc0], s0);                                     \
        cp16(&Bs[buf][bk1 * 136 + bc1], s1);                                     \
        cp_commit();                                                             \
    }

    float acc[2][8][4] = {};

    PROJ_ISSUE(0, 0);
    int cur = 0;
    for (int k0 = 0; k0 < 512; k0 += 16) {
        if (k0 + 16 < 512) { PROJ_ISSUE(cur ^ 1, k0 + 16); cp_wait<1>(); }
        else               { cp_wait<0>(); }
        __syncthreads();

        const float* Asc = As[cur];
        const float* Bsc = Bs[cur];
        #pragma unroll
        for (int kc = 0; kc < 16; kc += 8) {
            unsigned a[2][4], b[8][2];
            #pragma unroll
            for (int i = 0; i < 2; i++) {
                int mb = wm * 32 + i * 16;
                a[i][0] = __float_as_uint(Asc[(mb + g)     * 20 + kc + t]);
                a[i][1] = __float_as_uint(Asc[(mb + g + 8) * 20 + kc + t]);
                a[i][2] = __float_as_uint(Asc[(mb + g)     * 20 + kc + t + 4]);
                a[i][3] = __float_as_uint(Asc[(mb + g + 8) * 20 + kc + t + 4]);
            }
            #pragma unroll
            for (int j = 0; j < 8; j++) {
                int nb = wn * 64 + j * 8;
                b[j][0] = __float_as_uint(Bsc[(kc + t)     * 136 + nb + g]);
                b[j][1] = __float_as_uint(Bsc[(kc + t + 4) * 136 + nb + g]);
            }
            #pragma unroll
            for (int i = 0; i < 2; i++)
                #pragma unroll
                for (int j = 0; j < 8; j++)
                    mma_tf32(acc[i][j], a[i], b[j]);
        }
        __syncthreads();
        cur ^= 1;
    }
    #undef PROJ_ISSUE

    #pragma unroll
    for (int i = 0; i < 2; i++) {
        size_t r0 = bm + wm * 32 + i * 16 + g;
        #pragma unroll
        for (int j = 0; j < 8; j++) {
            int n = wn * 64 + j * 8 + 2 * t;
            if (vmode) {
                int gc = bn + n;
                float b0v = bv[gc], b1v = bv[gc + 1];
                *(float2*)(g_v + r0 * 512 + gc)       = make_float2(to_tf32(acc[i][j][0] + b0v), to_tf32(acc[i][j][1] + b1v));
                *(float2*)(g_v + (r0 + 8) * 512 + gc) = make_float2(to_tf32(acc[i][j][2] + b0v), to_tf32(acc[i][j][3] + b1v));
            } else {
                const float* bp = (wn == 0) ? bq : bk;
                int nn = (wn == 0) ? n : (n - 64);
                float b0v = bp[nn], b1v = bp[nn + 1];
                float* dst = (wn == 0) ? g_q : g_k;
                *(float2*)(dst + r0 * 64 + nn)       = make_float2(acc[i][j][0] + b0v, acc[i][j][1] + b1v);
                *(float2*)(dst + (r0 + 8) * 64 + nn) = make_float2(acc[i][j][2] + b0v, acc[i][j][3] + b1v);
            }
        }
    }
}

// =========================================================================
// Logits via 3xTF32 split mma (~fp32), single launch grid 1536 (R9).
// Writes RAW logits (softmax is fused into pv).
// =========================================================================
__global__ __launch_bounds__(256) void logits_kernel()
{
    __shared__ float Qs[96 * 68];
    __shared__ float Ks[96 * 68];

    const int tid  = threadIdx.x;
    const int lane = tid & 31, wid = tid >> 5;
    const int wm = wid & 1, wn = wid >> 1;   // 2 x 4
    const int g = lane >> 2, t = lane & 3;
    const int mode = blockIdx.x & 1;
    const int bid = blockIdx.x >> 1;

    size_t base; int stride;
    if (mode == 0) {
        int b = bid / NW, w = bid % NW;
        base = ((size_t)b * NH * NW + w) * NCQ;
        stride = NW * NCQ;
    } else {
        base = (size_t)bid * NW * NCQ;
        stride = NCQ;
    }
    float* __restrict__ out = (mode == 0 ? g_sv : g_sh) + (size_t)bid * 96 * 96;

    #pragma unroll
    for (int it = 0; it < 6; it++) {
        int idx = tid + it * 256;
        int r = idx >> 4, c4 = (idx & 15) * 4;
        *(float4*)&Qs[r * 68 + c4] = *(const float4*)(g_q + base + (size_t)r * stride + c4);
        *(float4*)&Ks[r * 68 + c4] = *(const float4*)(g_k + base + (size_t)r * stride + c4);
    }
    __syncthreads();

    float acc[3][3][4] = {};
    #pragma unroll
    for (int kc = 0; kc < 64; kc += 8) {
        unsigned ah[3][4], al[3][4], bh[3][2], bl[3][2];
        #pragma unroll
        for (int i = 0; i < 3; i++) {
            int mb = wm * 48 + i * 16;
            float f0 = Qs[(mb + g)     * 68 + kc + t];
            float f1 = Qs[(mb + g + 8) * 68 + kc + t];
            float f2 = Qs[(mb + g)     * 68 + kc + t + 4];
            float f3 = Qs[(mb + g + 8) * 68 + kc + t + 4];
            float h0 = to_tf32(f0), h1 = to_tf32(f1), h2 = to_tf32(f2), h3 = to_tf32(f3);
            ah[i][0] = __float_as_uint(h0); al[i][0] = __float_as_uint(to_tf32(f0 - h0));
            ah[i][1] = __float_as_uint(h1); al[i][1] = __float_as_uint(to_tf32(f1 - h1));
            ah[i][2] = __float_as_uint(h2); al[i][2] = __float_as_uint(to_tf32(f2 - h2));
            ah[i][3] = __float_as_uint(h3); al[i][3] = __float_as_uint(to_tf32(f3 - h3));
        }
        #pragma unroll
        for (int j = 0; j < 3; j++) {
            int nb = wn * 24 + j * 8;
            float f0 = Ks[(nb + g) * 68 + kc + t];
            float f1 = Ks[(nb + g) * 68 + kc + t + 4];
            float h0 = to_tf32(f0), h1 = to_tf32(f1);
            bh[j][0] = __float_as_uint(h0); bl[j][0] = __float_as_uint(to_tf32(f0 - h0));
            bh[j][1] = __float_as_uint(h1); bl[j][1] = __float_as_uint(to_tf32(f1 - h1));
        }
        #pragma unroll
        for (int i = 0; i < 3; i++)
            #pragma unroll
            for (int j = 0; j < 3; j++) {
                mma_tf32(acc[i][j], ah[i], bl[j]);   // hi*lo
                mma_tf32(acc[i][j], al[i], bh[j]);   // lo*hi
                mma_tf32(acc[i][j], ah[i], bh[j]);   // hi*hi (last: largest term)
            }
    }

    #pragma unroll
    for (int i = 0; i < 3; i++) {
        int r = wm * 48 + i * 16 + g;
        #pragma unroll
        for (int j = 0; j < 3; j++) {
            int c = wn * 24 + j * 8 + 2 * t;
            float v0 = acc[i][j][0], v1 = acc[i][j][1];
            float v2 = acc[i][j][2], v3 = acc[i][j][3];
            if (mode == 0) {
                if (r == c)         v0 = -1e30f;
                if (r == c + 1)     v1 = -1e30f;
                if (r + 8 == c)     v2 = -1e30f;
                if (r + 8 == c + 1) v3 = -1e30f;
            }
            *(float2*)(out + r * 96 + c)       = make_float2(v0, v1);
            *(float2*)(out + (r + 8) * 96 + c) = make_float2(v2, v3);
        }
    }
}

// =========================================================================
// PV with FUSED softmax, tf32 mma, cp.async double-buffered 32-row V tiles.
// Per block: load raw logits tile, joint-normalize each row against the
// other orientation's row (gmem), round probs to tf32 (same math as the
// old softmax kernel), then Y = P @ V over 4 n-chunks.
// mode 0: vertical   -> g_yv (bf16) ; mode 1: horizontal -> out.
// Dynamic smem: Ps 96x100 + Vs 2x32x136 = 73,216 B.
// =========================================================================
#define PV_SMEM_BYTES ((96 * 100 + 2 * 32 * 136) * 4)

__global__ __launch_bounds__(256) void pv_kernel(
    const float* __restrict__ x, const float* __restrict__ gamma_p,
    float* __restrict__ out, int mode)
{
    extern __shared__ float dsm[];
    float* Ps = dsm;              // 96*100
    float* Vsb = dsm + 9600;      // 2 x 32*136

    const int tid  = threadIdx.x;
    const int lane = tid & 31, wid = tid >> 5;
    const int wm = wid & 1, wn = wid >> 1;   // 2 x 4 warps
    const int g = lane >> 2, t = lane & 3;
    const int bid = blockIdx.x;

    const float* __restrict__ Pb = (mode == 0 ? g_sv : g_sh) + (size_t)bid * 9216;
    // other-orientation row base: token row r of this tile has its complementary
    // 96 logits at obase + r*9216 (contiguous 96 floats).
    const float* __restrict__ obase = (mode == 0 ? g_sh : g_sv)
        + (size_t)(bid / 96) * 884736 + (size_t)(bid % 96) * 96;

    size_t vrow0; int vstride;
    if (mode == 0) {
        int b = bid / NW, w = bid % NW;
        vrow0 = ((size_t)b * NH * NW + w) * NC;
        vstride = NW * NC;
    } else {
        vrow0 = (size_t)bid * NW * NC;
        vstride = NC;
    }

    // load raw logits tile (96x96 = 2304 float4, 9/thread)
    #pragma unroll
    for (int it = 0; it < 9; it++) {
        int idx = tid + it * 256;
        int m = idx / 24, c = idx % 24;
        *(float4*)&Ps[m * 100 + c * 4] = *(const float4*)(Pb + m * 96 + c * 4);
    }
    float gam = (mode == 1) ? *gamma_p : 0.f;
    __syncthreads();

    // fused joint softmax: warp wid normalizes rows wid*12 .. wid*12+11
    for (int rr = 0; rr < 12; rr++) {
        int row = wid * 12 + rr;
        const float* orow = obase + (size_t)row * 9216;
        float own[3], oth[3];
        #pragma unroll
        for (int i = 0; i < 3; i++) {
            own[i] = Ps[row * 100 + lane + 32 * i];
            oth[i] = orow[lane + 32 * i];
        }
        float m = fmaxf(fmaxf(fmaxf(own[0], own[1]), fmaxf(own[2], oth[0])),
                        fmaxf(oth[1], oth[2]));
        #pragma unroll
        for (int o = 16; o; o >>= 1) m = fmaxf(m, __shfl_xor_sync(0xffffffffu, m, o));
        float e[3], s = 0.f;
        #pragma unroll
        for (int i = 0; i < 3; i++) { e[i] = __expf(own[i] - m); s += e[i]; }
        #pragma unroll
        for (int i = 0; i < 3; i++) s += __expf(oth[i] - m);
        #pragma unroll
        for (int o = 16; o; o >>= 1) s += __shfl_xor_sync(0xffffffffu, s, o);
        float inv = 1.0f / s;
        #pragma unroll
        for (int i = 0; i < 3; i++)
            Ps[row * 100 + lane + 32 * i] = to_tf32(e[i] * inv);
    }
    __syncthreads();

    // V tile: 32 rows x 128 cols = 1024 float4, 4/thread
    #define PVV_ISSUE(buf, k0, ncc)                                              \
    {                                                                            \
        float* vb = Vsb + (buf) * 4352;                                          \
        _Pragma("unroll")                                                        \
        for (int it = 0; it < 4; it++) {                                         \
            int idx = tid + it * 256;                                            \
            int r = idx >> 5, c4 = (idx & 31) * 4;                               \
            cp16(&vb[r * 136 + c4],                                              \
                 g_v + vrow0 + (size_t)((k0) + r) * vstride + (ncc) + c4);       \
        }                                                                        \
        cp_commit();                                                             \
    }

    for (int nc = 0; nc < NC; nc += 128) {
        float acc[3][4][4] = {};

        PVV_ISSUE(0, 0, nc);
        int cur = 0;
        for (int k0 = 0; k0 < 96; k0 += 32) {
            if (k0 + 32 < 96) { PVV_ISSUE(cur ^ 1, k0 + 32, nc); cp_wait<1>(); }
            else              { cp_wait<0>(); }
            __syncthreads();

            const float* Vsc = Vsb + cur * 4352;
            #pragma unroll
            for (int kc = 0; kc < 32; kc += 8) {
                unsigned a[3][4], b[4][2];
                #pragma unroll
                for (int i = 0; i < 3; i++) {
                    int mb = wm * 48 + i * 16;
                    a[i][0] = __float_as_uint(Ps[(mb + g)     * 100 + k0 + kc + t]);
                    a[i][1] = __float_as_uint(Ps[(mb + g + 8) * 100 + k0 + kc + t]);
                    a[i][2] = __float_as_uint(Ps[(mb + g)     * 100 + k0 + kc + t + 4]);
                    a[i][3] = __float_as_uint(Ps[(mb + g + 8) * 100 + k0 + kc + t + 4]);
                }
                #pragma unroll
                for (int j = 0; j < 4; j++) {
                    int nb = wn * 32 + j * 8;
                    b[j][0] = __float_as_uint(Vsc[(kc + t)     * 136 + nb + g]);
                    b[j][1] = __float_as_uint(Vsc[(kc + t + 4) * 136 + nb + g]);
                }
                #pragma unroll
                for (int i = 0; i < 3; i++)
                    #pragma unroll
                    for (int j = 0; j < 4; j++)
                        mma_tf32(acc[i][j], a[i], b[j]);
            }
            __syncthreads();   // all warps done with Vs[cur] before refill
            cur ^= 1;
        }

        // Epilogue for this n-chunk
        #pragma unroll
        for (int i = 0; i < 3; i++) {
            int r0 = wm * 48 + i * 16 + g;
            #pragma unroll
            for (int j = 0; j < 4; j++) {
                int col = nc + wn * 32 + j * 8 + 2 * t;
                size_t o0 = vrow0 + (size_t)r0 * vstride + col;
                size_t o1 = vrow0 + (size_t)(r0 + 8) * vstride + col;
                if (mode == 0) {
                    *(__nv_bfloat162*)(g_yv + o0) = __floats2bfloat162_rn(acc[i][j][0], acc[i][j][1]);
                    *(__nv_bfloat162*)(g_yv + o1) = __floats2bfloat162_rn(acc[i][j][2], acc[i][j][3]);
                } else {
                    float2 yv0 = __bfloat1622float2(*(const __nv_bfloat162*)(g_yv + o0));
                    float2 yv1 = __bfloat1622float2(*(const __nv_bfloat162*)(g_yv + o1));
                    float2 x0  = *(const float2*)(x + o0);
                    float2 x1  = *(const float2*)(x + o1);
                    *(float2*)(out + o0) = make_float2(x0.x + gam * (yv0.x + acc[i][j][0]),
                                                       x0.y + gam * (yv0.y + acc[i][j][1]));
                    *(float2*)(out + o1) = make_float2(x1.x + gam * (yv1.x + acc[i][j][2]),
                                                       x1.y + gam * (yv1.y + acc[i][j][3]));
                }
            }
        }
    }
    #undef PVV_ISSUE
}

// =========================================================================
extern "C" void kernel_launch(void* const* d_in, const int* in_sizes, int n_in,
                              void* d_out, int out_size)
{
    const float* x     = (const float*)d_in[0];
    const float* Wq    = (const float*)d_in[1];
    const float* bq    = (const float*)d_in[2];
    const float* Wk    = (const float*)d_in[3];
    const float* bk    = (const float*)d_in[4];
    const float* Wv    = (const float*)d_in[5];
    const float* bv    = (const float*)d_in[6];
    const float* gamma = (const float*)d_in[7];
    float* out = (float*)d_out;
    (void)in_sizes; (void)n_in; (void)out_size;

    cudaFuncSetAttribute(pv_kernel,
                         cudaFuncAttributeMaxDynamicSharedMemorySize, PV_SMEM_BYTES);

    // All projections in ONE launch (tf32 mma, cp.async; x read once via L2)
    proj_kernel<<<dim3(5, 576), 256>>>(x, Wq, Wk, Wv, bq, bk, bv);

    // Logits, both modes in one launch (3xTF32 split mma) — RAW logits
    logits_kernel<<<2 * NB * NW, 256>>>();

    // Attention-value with fused joint softmax (tf32 mma, cp.async)
    pv_kernel<<<NB * NW, 256, PV_SMEM_BYTES>>>(x, gamma, out, 0);
    pv_kernel<<<NB * NH, 256, PV_SMEM_BYTES>>>(x, gamma, out, 1);
}

// round 12
// speedup vs baseline: 1.0498x; 1.0498x over previous
#include <cuda_runtime.h>
#include <cuda_bf16.h>
#include <cstddef>

#define NB 8
#define NH 96
#define NW 96
#define NC 512
#define NCQ 64
#define NT (NB*NH*NW)   // 73728 tokens

typedef unsigned long long u64;

// ---------------- scratch (device globals; no runtime allocation) --------
__device__ float g_q[(size_t)NT*NCQ];            // [t][64]
__device__ float g_k[(size_t)NT*NCQ];            // [t][64]
__device__ float g_v[(size_t)NT*NC];             // [t][512] (tf32-rounded)
__device__ float g_sv[(size_t)NB*NW*NH*NH];      // [b][w][h][g] logits/probs
__device__ float g_sh[(size_t)NT*NW];            // [b][h][w][u] logits/probs
__device__ __nv_bfloat16 g_yv[(size_t)NT*NC];    // [t][512] bf16 (residual path)

// ---------------- helpers ------------------------------------------------
__device__ __forceinline__ float to_tf32(float x) {
    unsigned u; asm("cvt.rna.tf32.f32 %0, %1;" : "=r"(u) : "f"(x));
    return __uint_as_float(u);
}
__device__ __forceinline__ void mma_tf32(float (&c)[4], const unsigned (&a)[4],
                                         const unsigned (&b)[2]) {
    asm volatile(
        "mma.sync.aligned.m16n8k8.row.col.f32.tf32.tf32.f32 "
        "{%0,%1,%2,%3}, {%4,%5,%6,%7}, {%8,%9}, {%0,%1,%2,%3};\n"
        : "+f"(c[0]), "+f"(c[1]), "+f"(c[2]), "+f"(c[3])
        : "r"(a[0]), "r"(a[1]), "r"(a[2]), "r"(a[3]),
          "r"(b[0]), "r"(b[1]));
}
__device__ __forceinline__ void cp16(void* s, const void* g) {
    unsigned sa = (unsigned)__cvta_generic_to_shared(s);
    asm volatile("cp.async.ca.shared.global [%0], [%1], 16;" :: "r"(sa), "l"(g));
}
__device__ __forceinline__ void cp_commit() {
    asm volatile("cp.async.commit_group;");
}
template<int N> __device__ __forceinline__ void cp_wait() {
    asm volatile("cp.async.wait_group %0;" :: "n"(N));
}

// =========================================================================
// Merged projection GEMM via tf32 mma, cp.async double-buffered.
// grid (5, 576): blockIdx.x = 0..3 -> v chunk (output g_v tf32-rounded);
// blockIdx.x = 4 -> q|k.  BM=128, BK=16, 256 thr, warp grid 4m x 2n.
// =========================================================================
__global__ __launch_bounds__(256) void proj_kernel(
    const float* __restrict__ A,  const float* __restrict__ Wq,
    const float* __restrict__ Wk, const float* __restrict__ Wv,
    const float* __restrict__ bq, const float* __restrict__ bk,
    const float* __restrict__ bv)
{
    __shared__ float As[2][128 * 20];
    __shared__ float Bs[2][16 * 136];

    const int tid  = threadIdx.x;
    const int lane = tid & 31, wid = tid >> 5;
    const int wm = wid & 3, wn = wid >> 2;   // 4 x 2 warps, warp tile 32x64
    const int g = lane >> 2, t = lane & 3;
    const size_t bm = (size_t)blockIdx.y * 128;
    const int vmode = (blockIdx.x < 4);
    const int bn = vmode ? blockIdx.x * 128 : 0;

    const int am0 = tid >> 2,         ac0 = (tid & 3) * 4;
    const int am1 = (tid + 256) >> 2, ac1 = ((tid + 256) & 3) * 4;
    const int bk0 = tid >> 5,         bc0 = (tid & 31) * 4;
    const int bk1 = (tid + 256) >> 5, bc1 = ((tid + 256) & 31) * 4;

    #define PROJ_ISSUE(buf, k0)                                                  \
    {                                                                            \
        cp16(&As[buf][am0 * 20 + ac0], A + (bm + am0) * 512 + (k0) + ac0);       \
        cp16(&As[buf][am1 * 20 + ac1], A + (bm + am1) * 512 + (k0) + ac1);       \
        const float* s0, *s1;                                                    \
        if (vmode) {                                                             \
            s0 = Wv + (size_t)((k0) + bk0) * 512 + bn + bc0;                     \
            s1 = Wv + (size_t)((k0) + bk1) * 512 + bn + bc1;                     \
        } else {                                                                 \
            s0 = (bc0 < 64) ? (Wq + (size_t)((k0) + bk0) * 64 + bc0)             \
                            : (Wk + (size_t)((k0) + bk0) * 64 + bc0 - 64);       \
            s1 = (bc1 < 64) ? (Wq + (size_t)((k0) + bk1) * 64 + bc1)             \
                            : (Wk + (size_t)((k0) + bk1) * 64 + bc1 - 64);       \
        }                                                                        \
        cp16(&Bs[buf][bk0 * 136 + bc0], s0);                                     \
        cp16(&Bs[buf][bk1 * 136 + bc1], s1);                                     \
        cp_commit();                                                             \
    }

    float acc[2][8][4] = {};

    PROJ_ISSUE(0, 0);
    int cur = 0;
    for (int k0 = 0; k0 < 512; k0 += 16) {
        if (k0 + 16 < 512) { PROJ_ISSUE(cur ^ 1, k0 + 16); cp_wait<1>(); }
        else               { cp_wait<0>(); }
        __syncthreads();

        const float* Asc = As[cur];
        const float* Bsc = Bs[cur];
        #pragma unroll
        for (int kc = 0; kc < 16; kc += 8) {
            unsigned a[2][4], b[8][2];
            #pragma unroll
            for (int i = 0; i < 2; i++) {
                int mb = wm * 32 + i * 16;
                a[i][0] = __float_as_uint(Asc[(mb + g)     * 20 + kc + t]);
                a[i][1] = __float_as_uint(Asc[(mb + g + 8) * 20 + kc + t]);
                a[i][2] = __float_as_uint(Asc[(mb + g)     * 20 + kc + t + 4]);
                a[i][3] = __float_as_uint(Asc[(mb + g + 8) * 20 + kc + t + 4]);
            }
            #pragma unroll
            for (int j = 0; j < 8; j++) {
                int nb = wn * 64 + j * 8;
                b[j][0] = __float_as_uint(Bsc[(kc + t)     * 136 + nb + g]);
                b[j][1] = __float_as_uint(Bsc[(kc + t + 4) * 136 + nb + g]);
            }
            #pragma unroll
            for (int i = 0; i < 2; i++)
                #pragma unroll
                for (int j = 0; j < 8; j++)
                    mma_tf32(acc[i][j], a[i], b[j]);
        }
        __syncthreads();
        cur ^= 1;
    }
    #undef PROJ_ISSUE

    #pragma unroll
    for (int i = 0; i < 2; i++) {
        size_t r0 = bm + wm * 32 + i * 16 + g;
        #pragma unroll
        for (int j = 0; j < 8; j++) {
            int n = wn * 64 + j * 8 + 2 * t;
            if (vmode) {
                int gc = bn + n;
                float b0v = bv[gc], b1v = bv[gc + 1];
                *(float2*)(g_v + r0 * 512 + gc)       = make_float2(to_tf32(acc[i][j][0] + b0v), to_tf32(acc[i][j][1] + b1v));
                *(float2*)(g_v + (r0 + 8) * 512 + gc) = make_float2(to_tf32(acc[i][j][2] + b0v), to_tf32(acc[i][j][3] + b1v));
            } else {
                const float* bp = (wn == 0) ? bq : bk;
                int nn = (wn == 0) ? n : (n - 64);
                float b0v = bp[nn], b1v = bp[nn + 1];
                float* dst = (wn == 0) ? g_q : g_k;
                *(float2*)(dst + r0 * 64 + nn)       = make_float2(acc[i][j][0] + b0v, acc[i][j][1] + b1v);
                *(float2*)(dst + (r0 + 8) * 64 + nn) = make_float2(acc[i][j][2] + b0v, acc[i][j][3] + b1v);
            }
        }
    }
}

// =========================================================================
// Logits via 3xTF32 split mma (~fp32 accuracy on tensor pipe).
// Single launch, grid 1536: mode = bid & 1, tile index = bid >> 1.
// =========================================================================
__global__ __launch_bounds__(256) void logits_kernel()
{
    __shared__ float Qs[96 * 68];
    __shared__ float Ks[96 * 68];

    const int tid  = threadIdx.x;
    const int lane = tid & 31, wid = tid >> 5;
    const int wm = wid & 1, wn = wid >> 1;   // 2 x 4
    const int g = lane >> 2, t = lane & 3;
    const int mode = blockIdx.x & 1;
    const int bid = blockIdx.x >> 1;

    size_t base; int stride;
    if (mode == 0) {
        int b = bid / NW, w = bid % NW;
        base = ((size_t)b * NH * NW + w) * NCQ;
        stride = NW * NCQ;
    } else {
        base = (size_t)bid * NW * NCQ;
        stride = NCQ;
    }
    float* __restrict__ out = (mode == 0 ? g_sv : g_sh) + (size_t)bid * 96 * 96;

    #pragma unroll
    for (int it = 0; it < 6; it++) {
        int idx = tid + it * 256;
        int r = idx >> 4, c4 = (idx & 15) * 4;
        *(float4*)&Qs[r * 68 + c4] = *(const float4*)(g_q + base + (size_t)r * stride + c4);
        *(float4*)&Ks[r * 68 + c4] = *(const float4*)(g_k + base + (size_t)r * stride + c4);
    }
    __syncthreads();

    float acc[3][3][4] = {};
    #pragma unroll
    for (int kc = 0; kc < 64; kc += 8) {
        unsigned ah[3][4], al[3][4], bh[3][2], bl[3][2];
        #pragma unroll
        for (int i = 0; i < 3; i++) {
            int mb = wm * 48 + i * 16;
            float f0 = Qs[(mb + g)     * 68 + kc + t];
            float f1 = Qs[(mb + g + 8) * 68 + kc + t];
            float f2 = Qs[(mb + g)     * 68 + kc + t + 4];
            float f3 = Qs[(mb + g + 8) * 68 + kc + t + 4];
            float h0 = to_tf32(f0), h1 = to_tf32(f1), h2 = to_tf32(f2), h3 = to_tf32(f3);
            ah[i][0] = __float_as_uint(h0); al[i][0] = __float_as_uint(to_tf32(f0 - h0));
            ah[i][1] = __float_as_uint(h1); al[i][1] = __float_as_uint(to_tf32(f1 - h1));
            ah[i][2] = __float_as_uint(h2); al[i][2] = __float_as_uint(to_tf32(f2 - h2));
            ah[i][3] = __float_as_uint(h3); al[i][3] = __float_as_uint(to_tf32(f3 - h3));
        }
        #pragma unroll
        for (int j = 0; j < 3; j++) {
            int nb = wn * 24 + j * 8;
            float f0 = Ks[(nb + g) * 68 + kc + t];
            float f1 = Ks[(nb + g) * 68 + kc + t + 4];
            float h0 = to_tf32(f0), h1 = to_tf32(f1);
            bh[j][0] = __float_as_uint(h0); bl[j][0] = __float_as_uint(to_tf32(f0 - h0));
            bh[j][1] = __float_as_uint(h1); bl[j][1] = __float_as_uint(to_tf32(f1 - h1));
        }
        #pragma unroll
        for (int i = 0; i < 3; i++)
            #pragma unroll
            for (int j = 0; j < 3; j++) {
                mma_tf32(acc[i][j], ah[i], bl[j]);   // hi*lo
                mma_tf32(acc[i][j], al[i], bh[j]);   // lo*hi
                mma_tf32(acc[i][j], ah[i], bh[j]);   // hi*hi (last: largest term)
            }
    }

    #pragma unroll
    for (int i = 0; i < 3; i++) {
        int r = wm * 48 + i * 16 + g;
        #pragma unroll
        for (int j = 0; j < 3; j++) {
            int c = wn * 24 + j * 8 + 2 * t;
            float v0 = acc[i][j][0], v1 = acc[i][j][1];
            float v2 = acc[i][j][2], v3 = acc[i][j][3];
            if (mode == 0) {
                if (r == c)         v0 = -1e30f;
                if (r == c + 1)     v1 = -1e30f;
                if (r + 8 == c)     v2 = -1e30f;
                if (r + 8 == c + 1) v3 = -1e30f;
            }
            *(float2*)(out + r * 96 + c)       = make_float2(v0, v1);
            *(float2*)(out + (r + 8) * 96 + c) = make_float2(v2, v3);
        }
    }
}

// =========================================================================
// Softmax over 192 concatenated logits per token; writes tf32-rounded probs.
// =========================================================================
__global__ void softmax_kernel()
{
    int gw = (int)((blockIdx.x * blockDim.x + threadIdx.x) >> 5);
    int lane = threadIdx.x & 31;
    if (gw >= NT) return;
    int b = gw / (NH * NW), rem = gw % (NH * NW);
    int h = rem / NW, w = rem % NW;

    float* __restrict__ svp = g_sv + (((size_t)b * NW + w) * NH + h) * NH;
    float* __restrict__ shp = g_sh + (size_t)gw * NW;

    float v[6];
    float m = -3.4e38f;
    #pragma unroll
    for (int i = 0; i < 3; i++) { v[i]     = svp[lane + 32 * i]; m = fmaxf(m, v[i]); }
    #pragma unroll
    for (int i = 0; i < 3; i++) { v[3 + i] = shp[lane + 32 * i]; m = fmaxf(m, v[3 + i]); }
    #pragma unroll
    for (int o = 16; o; o >>= 1) m = fmaxf(m, __shfl_xor_sync(0xffffffffu, m, o));

    float s = 0.f;
    #pragma unroll
    for (int i = 0; i < 6; i++) { v[i] = __expf(v[i] - m); s += v[i]; }
    #pragma unroll
    for (int o = 16; o; o >>= 1) s += __shfl_xor_sync(0xffffffffu, s, o);
    float inv = 1.0f / s;

    #pragma unroll
    for (int i = 0; i < 3; i++) svp[lane + 32 * i] = to_tf32(v[i] * inv);
    #pragma unroll
    for (int i = 0; i < 3; i++) shp[lane + 32 * i] = to_tf32(v[3 + i] * inv);
}

// =========================================================================
// PV via tf32 mma, cp.async double-buffered V tiles.
// Y(96x512) = P(96x96) @ V(96x512); P loaded once per block,
// 4 internal n-chunks of 128. 256 thr; warp grid 2m x 4n (48x32).
// __launch_bounds__(256, 3): cap regs at 85 -> 3 CTAs/SM (occupancy lever).
// mode 0: vertical   -> g_yv (bf16) ; mode 1: horizontal -> out.
// =========================================================================
__global__ __launch_bounds__(256, 3) void pv_kernel(
    const float* __restrict__ x, const float* __restrict__ gamma_p,
    float* __restrict__ out, int mode)
{
    __shared__ float Ps[96 * 100];      // 38,400 B
    __shared__ float Vs[2][16 * 136];   // 2 x 8,704 B

    const int tid  = threadIdx.x;
    const int lane = tid & 31, wid = tid >> 5;
    const int wm = wid & 1, wn = wid >> 1;   // 2 x 4 warps
    const int g = lane >> 2, t = lane & 3;
    const int bid = blockIdx.x;

    const float* __restrict__ Pb = (mode == 0 ? g_sv : g_sh) + (size_t)bid * 96 * 96;
    size_t vrow0; int vstride;
    if (mode == 0) {
        int b = bid / NW, w = bid % NW;
        vrow0 = ((size_t)b * NH * NW + w) * NC;
        vstride = NW * NC;
    } else {
        vrow0 = (size_t)bid * NW * NC;
        vstride = NC;
    }

    // load P once (96x96 = 2304 float4, 9/thread); probs already tf32-rounded
    #pragma unroll
    for (int it = 0; it < 9; it++) {
        int idx = tid + it * 256;
        int m = idx / 24, c = idx % 24;
        *(float4*)&Ps[m * 100 + c * 4] = *(const float4*)(Pb + m * 96 + c * 4);
    }
    float gam = (mode == 1) ? *gamma_p : 0.f;

    // V tile: 16 rows x 128 cols = 512 float4, 2/thread
    const int vk0 = tid >> 5,         vc0 = (tid & 31) * 4;
    const int vk1 = (tid + 256) >> 5, vc1 = ((tid + 256) & 31) * 4;

    #define PVV_ISSUE(buf, k0, ncc)                                              \
    {                                                                            \
        cp16(&Vs[buf][vk0 * 136 + vc0],                                          \
             g_v + vrow0 + (size_t)((k0) + vk0) * vstride + (ncc) + vc0);        \
        cp16(&Vs[buf][vk1 * 136 + vc1],                                          \
             g_v + vrow0 + (size_t)((k0) + vk1) * vstride + (ncc) + vc1);        \
        cp_commit();                                                             \
    }

    for (int nc = 0; nc < NC; nc += 128) {
        float acc[3][4][4] = {};

        PVV_ISSUE(0, 0, nc);
        int cur = 0;
        for (int k0 = 0; k0 < 96; k0 += 16) {
            if (k0 + 16 < 96) { PVV_ISSUE(cur ^ 1, k0 + 16, nc); cp_wait<1>(); }
            else              { cp_wait<0>(); }
            __syncthreads();   // Vs[cur] ready for all; Ps done on first pass

            const float* Vsc = Vs[cur];
            #pragma unroll
            for (int kc = 0; kc < 16; kc += 8) {
                unsigned a[3][4], b[4][2];
                #pragma unroll
                for (int i = 0; i < 3; i++) {
                    int mb = wm * 48 + i * 16;
                    a[i][0] = __float_as_uint(Ps[(mb + g)     * 100 + k0 + kc + t]);
                    a[i][1] = __float_as_uint(Ps[(mb + g + 8) * 100 + k0 + kc + t]);
                    a[i][2] = __float_as_uint(Ps[(mb + g)     * 100 + k0 + kc + t + 4]);
                    a[i][3] = __float_as_uint(Ps[(mb + g + 8) * 100 + k0 + kc + t + 4]);
                }
                #pragma unroll
                for (int j = 0; j < 4; j++) {
                    int nb = wn * 32 + j * 8;
                    b[j][0] = __float_as_uint(Vsc[(kc + t)     * 136 + nb + g]);
                    b[j][1] = __float_as_uint(Vsc[(kc + t + 4) * 136 + nb + g]);
                }
                #pragma unroll
                for (int i = 0; i < 3; i++)
                    #pragma unroll
                    for (int j = 0; j < 4; j++)
                        mma_tf32(acc[i][j], a[i], b[j]);
            }
            __syncthreads();   // all warps done with Vs[cur] before refill
            cur ^= 1;
        }

        // Epilogue for this n-chunk
        #pragma unroll
        for (int i = 0; i < 3; i++) {
            int r0 = wm * 48 + i * 16 + g;
            #pragma unroll
            for (int j = 0; j < 4; j++) {
                int col = nc + wn * 32 + j * 8 + 2 * t;
                size_t o0 = vrow0 + (size_t)r0 * vstride + col;
                size_t o1 = vrow0 + (size_t)(r0 + 8) * vstride + col;
                if (mode == 0) {
                    *(__nv_bfloat162*)(g_yv + o0) = __floats2bfloat162_rn(acc[i][j][0], acc[i][j][1]);
                    *(__nv_bfloat162*)(g_yv + o1) = __floats2bfloat162_rn(acc[i][j][2], acc[i][j][3]);
                } else {
                    float2 yv0 = __bfloat1622float2(*(const __nv_bfloat162*)(g_yv + o0));
                    float2 yv1 = __bfloat1622float2(*(const __nv_bfloat162*)(g_yv + o1));
                    float2 x0  = *(const float2*)(x + o0);
                    float2 x1  = *(const float2*)(x + o1);
                    *(float2*)(out + o0) = make_float2(x0.x + gam * (yv0.x + acc[i][j][0]),
                                                       x0.y + gam * (yv0.y + acc[i][j][1]));
                    *(float2*)(out + o1) = make_float2(x1.x + gam * (yv1.x + acc[i][j][2]),
                                                       x1.y + gam * (yv1.y + acc[i][j][3]));
                }
            }
        }
    }
    #undef PVV_ISSUE
}

// =========================================================================
extern "C" void kernel_launch(void* const* d_in, const int* in_sizes, int n_in,
                              void* d_out, int out_size)
{
    const float* x     = (const float*)d_in[0];
    const float* Wq    = (const float*)d_in[1];
    const float* bq    = (const float*)d_in[2];
    const float* Wk    = (const float*)d_in[3];
    const float* bk    = (const float*)d_in[4];
    const float* Wv    = (const float*)d_in[5];
    const float* bv    = (const float*)d_in[6];
    const float* gamma = (const float*)d_in[7];
    float* out = (float*)d_out;
    (void)in_sizes; (void)n_in; (void)out_size;

    // All projections in ONE launch (tf32 mma, cp.async; x read once via L2)
    proj_kernel<<<dim3(5, 576), 256>>>(x, Wq, Wk, Wv, bq, bk, bv);

    // Logits, both modes in one launch (3xTF32 split mma)
    logits_kernel<<<2 * NB * NW, 256>>>();

    // Joint softmax (writes tf32-rounded probs)
    softmax_kernel<<<NT / 8, 256>>>();

    // Attention-value (tf32 mma, cp.async pipelined) + epilogue
    pv_kernel<<<NB * NW, 256>>>(x, gamma, out, 0);
    pv_kernel<<<NB * NH, 256>>>(x, gamma, out, 1);
}